// round 1
// baseline (speedup 1.0000x reference)
#include <cuda_runtime.h>
#include <cstdint>

#define BATCH 512
#define SEQ   512
#define EMB   128
#define HID   64
#define GATES 256   // 4*HID

// 268 MB scratch for xproj0 = emb[seq] @ Wih0^T + b0, layout [(b*SEQ+s)][GATES]
__device__ float g_xp0[(size_t)BATCH * SEQ * GATES];

// ---------------- packed f32x2 helpers ----------------
static __device__ __forceinline__ unsigned long long pk2(float lo, float hi) {
    unsigned long long v;
    asm("mov.b64 %0, {%1, %2};" : "=l"(v) : "f"(lo), "f"(hi));
    return v;
}
static __device__ __forceinline__ void upk2(unsigned long long v, float& lo, float& hi) {
    asm("mov.b64 {%0, %1}, %2;" : "=f"(lo), "=f"(hi) : "l"(v));
}
static __device__ __forceinline__ void fma2(unsigned long long& a,
                                            unsigned long long x,
                                            unsigned long long w) {
    asm("fma.rn.f32x2 %0, %1, %2, %0;" : "+l"(a) : "l"(x), "l"(w));
}
static __device__ __forceinline__ float tanh_f(float x) {
    float y;
    asm("tanh.approx.f32 %0, %1;" : "=f"(y) : "f"(x));
    return y;
}
static __device__ __forceinline__ float sig_f(float x) {
    return fmaf(0.5f, tanh_f(0.5f * x), 0.5f);
}

// ======================================================================
// Kernel 1: xproj0[row][g] = b0[g] + dot(emb[seq[row]], Wih0[g][:])
// 2048 blocks x 256 threads; each block: 4 tiles of 32 rows, Wih0 in smem.
// ======================================================================
#define K1_WS_STRIDE 132   // padded row stride for Wih0 in smem (bank-safe)

__global__ void __launch_bounds__(256)
k_xproj(const int* __restrict__ seq32,   // raw words of input_seq (int32 or int64)
        const float* __restrict__ emb,
        const float* __restrict__ Wih,
        const float* __restrict__ bih,
        const float* __restrict__ bhh,
        float* __restrict__ xp)
{
    extern __shared__ float sm[];
    float* ws   = sm;                         // 256 * 132
    float* xs   = ws + 256 * K1_WS_STRIDE;    // 32 * 128
    int*   sidx = (int*)(xs + 32 * EMB);      // 32

    const int tid = threadIdx.x;

    // Detect int64 vs int32 input_seq: int64 little-endian with values <2^31
    // has all-zero odd 32-bit words.
    const bool is64 = ((__ldg(seq32 + 1) | __ldg(seq32 + 3) | __ldg(seq32 + 5) |
                        __ldg(seq32 + 7) | __ldg(seq32 + 9) | __ldg(seq32 + 11) |
                        __ldg(seq32 + 13) | __ldg(seq32 + 15)) == 0);

    // Stage Wih0 into padded smem
    for (int j = tid; j < 256 * EMB; j += 256)
        ws[(j >> 7) * K1_WS_STRIDE + (j & 127)] = Wih[j];

    const float b0 = bih[tid] + bhh[tid];
    const int base = blockIdx.x * 128;

    for (int tile = 0; tile < 4; ++tile) {
        const int row0 = base + tile * 32;
        __syncthreads();                       // xs/ws reuse barrier
        if (tid < 32) {
            int row = row0 + tid;
            int idx = is64 ? __ldg(seq32 + 2 * row) : __ldg(seq32 + row);
            sidx[tid] = idx * EMB;
        }
        __syncthreads();
        // Gather 32 embedding rows
        for (int j = tid; j < 32 * 32; j += 256) {
            int r = j >> 5, k4 = (j & 31) << 2;
            *(float4*)&xs[r * EMB + k4] = *(const float4*)&emb[sidx[r] + k4];
        }
        __syncthreads();

        unsigned long long acc[32];
#pragma unroll
        for (int r = 0; r < 32; ++r) acc[r] = pk2(b0, 0.f);

#pragma unroll 2
        for (int kc = 0; kc < 32; ++kc) {
            const ulonglong2 w = *(const ulonglong2*)&ws[tid * K1_WS_STRIDE + kc * 4];
#pragma unroll
            for (int r = 0; r < 32; ++r) {
                const ulonglong2 x = *(const ulonglong2*)&xs[r * EMB + kc * 4];
                fma2(acc[r], x.x, w.x);
                fma2(acc[r], x.y, w.y);
            }
        }
#pragma unroll
        for (int r = 0; r < 32; ++r) {
            float lo, hi;
            upk2(acc[r], lo, hi);
            xp[(size_t)(row0 + r) * GATES + tid] = lo + hi;
        }
    }
}

// ======================================================================
// Kernel 2: fused 2-layer LSTM scan + final FC.
// 128 blocks x 256 threads; block b owns batch rows 4b..4b+3 for all 512
// steps of BOTH layers. Whh0/Wih1/Whh1 in smem (pad 68). c-state in regs.
// ======================================================================
#define WS 68   // padded weight row stride (bank-safe for LDS.128)

__global__ void __launch_bounds__(256)
k_scan(const float* __restrict__ xp,
       const float* __restrict__ Whh0, const float* __restrict__ Wih1,
       const float* __restrict__ Whh1,
       const float* __restrict__ bih1, const float* __restrict__ bhh1,
       const float* __restrict__ Wfc,  const float* __restrict__ bfc,
       float* __restrict__ out)
{
    extern __shared__ float sm[];
    float* w0s = sm;                    // 256*68
    float* w1i = w0s + 256 * WS;        // 256*68
    float* w1h = w1i + 256 * WS;        // 256*68
    float* h0s = w1h + 256 * WS;        // 4*64
    float* h1s = h0s + 256;             // 4*64
    float* gb  = h1s + 256;             // 4*256 (gate exchange, reused per layer)
    float* b1s = gb + 1024;             // 256

    const int tid = threadIdx.x;
    for (int j = tid; j < 256 * HID; j += 256) {
        int g = j >> 6, k = j & 63;
        w0s[g * WS + k] = Whh0[j];
        w1i[g * WS + k] = Wih1[j];
        w1h[g * WS + k] = Whh1[j];
    }
    b1s[tid] = bih1[tid] + bhh1[tid];
    h0s[tid] = 0.f;
    h1s[tid] = 0.f;

    const int rr = tid >> 6, u = tid & 63;
    float c0 = 0.f, c1 = 0.f;
    const int row0 = blockIdx.x * 4;

    const float* p[4];
#pragma unroll
    for (int r = 0; r < 4; ++r)
        p[r] = xp + (size_t)(row0 + r) * SEQ * GATES + tid;

    __syncthreads();

    float xpc[4];
#pragma unroll
    for (int r = 0; r < 4; ++r) xpc[r] = __ldg(p[r]);

    for (int t = 0; t < SEQ; ++t) {
        // prefetch next step's xproj column
        float xpn[4] = {0.f, 0.f, 0.f, 0.f};
        if (t < SEQ - 1) {
#pragma unroll
            for (int r = 0; r < 4; ++r)
                xpn[r] = __ldg(p[r] + (size_t)(t + 1) * GATES);
        }

        // ---- Phase A: layer0 gates = xproj + h0 @ Whh0^T (thread = gate tid)
        unsigned long long a0[4];
#pragma unroll
        for (int r = 0; r < 4; ++r) a0[r] = pk2(xpc[r], 0.f);
#pragma unroll
        for (int kc = 0; kc < 16; ++kc) {
            const ulonglong2 w = *(const ulonglong2*)&w0s[tid * WS + kc * 4];
#pragma unroll
            for (int r = 0; r < 4; ++r) {
                const ulonglong2 h = *(const ulonglong2*)&h0s[r * HID + kc * 4];
                fma2(a0[r], h.x, w.x);
                fma2(a0[r], h.y, w.y);
            }
        }
#pragma unroll
        for (int r = 0; r < 4; ++r) {
            float lo, hi; upk2(a0[r], lo, hi);
            gb[r * GATES + tid] = lo + hi;
        }
        __syncthreads();

        // ---- Phase B: layer0 elementwise (thread = (row rr, unit u))
        {
            const float* gr = gb + rr * GATES;
            float gi = sig_f(gr[u]);
            float gf = sig_f(gr[64 + u]);
            float gg = tanh_f(gr[128 + u]);
            float go = sig_f(gr[192 + u]);
            c0 = gf * c0 + gi * gg;
            h0s[rr * HID + u] = go * tanh_f(c0);
        }
        __syncthreads();

        // ---- Phase C: layer1 gates = b1 + h0new @ Wih1^T + h1 @ Whh1^T
        unsigned long long a1[4];
#pragma unroll
        for (int r = 0; r < 4; ++r) a1[r] = pk2(b1s[tid], 0.f);
#pragma unroll
        for (int kc = 0; kc < 16; ++kc) {
            const ulonglong2 wi = *(const ulonglong2*)&w1i[tid * WS + kc * 4];
            const ulonglong2 wh = *(const ulonglong2*)&w1h[tid * WS + kc * 4];
#pragma unroll
            for (int r = 0; r < 4; ++r) {
                const ulonglong2 h0v = *(const ulonglong2*)&h0s[r * HID + kc * 4];
                fma2(a1[r], h0v.x, wi.x);
                fma2(a1[r], h0v.y, wi.y);
                const ulonglong2 h1v = *(const ulonglong2*)&h1s[r * HID + kc * 4];
                fma2(a1[r], h1v.x, wh.x);
                fma2(a1[r], h1v.y, wh.y);
            }
        }
#pragma unroll
        for (int r = 0; r < 4; ++r) {
            float lo, hi; upk2(a1[r], lo, hi);
            gb[r * GATES + tid] = lo + hi;
        }
        __syncthreads();

        // ---- Phase D: layer1 elementwise
        {
            const float* gr = gb + rr * GATES;
            float gi = sig_f(gr[u]);
            float gf = sig_f(gr[64 + u]);
            float gg = tanh_f(gr[128 + u]);
            float go = sig_f(gr[192 + u]);
            c1 = gf * c1 + gi * gg;
            h1s[rr * HID + u] = go * tanh_f(c1);
        }
        __syncthreads();

#pragma unroll
        for (int r = 0; r < 4; ++r) xpc[r] = xpn[r];
    }

    // ---- Final FC + sigmoid on last h1 (8 outputs per block)
    if (tid < 8) {
        int r = tid >> 1, o = tid & 1;
        float a = __ldg(&bfc[o]);
        for (int k = 0; k < HID; ++k)
            a = fmaf(h1s[r * HID + k], __ldg(&Wfc[o * HID + k]), a);
        out[(row0 + r) * 2 + o] = sig_f(a);
    }
}

// ======================================================================
extern "C" void kernel_launch(void* const* d_in, const int* in_sizes, int n_in,
                              void* d_out, int out_size) {
    const int*   seq32 = (const int*)d_in[0];   // int32 or raw words of int64
    const float* emb   = (const float*)d_in[1];
    const float* Wih0  = (const float*)d_in[2];
    const float* Whh0  = (const float*)d_in[3];
    const float* bih0  = (const float*)d_in[4];
    const float* bhh0  = (const float*)d_in[5];
    const float* Wih1  = (const float*)d_in[6];
    const float* Whh1  = (const float*)d_in[7];
    const float* bih1  = (const float*)d_in[8];
    const float* bhh1  = (const float*)d_in[9];
    const float* Wfc   = (const float*)d_in[10];
    const float* bfc   = (const float*)d_in[11];
    float* out = (float*)d_out;

    float* xp = nullptr;
    cudaGetSymbolAddress((void**)&xp, g_xp0);

    const int smem1 = (256 * K1_WS_STRIDE + 32 * EMB) * 4 + 32 * 4;
    const int smem2 = (3 * 256 * WS + 256 + 256 + 1024 + 256) * 4;
    cudaFuncSetAttribute(k_xproj, cudaFuncAttributeMaxDynamicSharedMemorySize, smem1);
    cudaFuncSetAttribute(k_scan,  cudaFuncAttributeMaxDynamicSharedMemorySize, smem2);

    k_xproj<<<(BATCH * SEQ) / 128, 256, smem1>>>(seq32, emb, Wih0, bih0, bhh0, xp);
    k_scan<<<BATCH / 4, 256, smem2>>>(xp, Whh0, Wih1, Whh1, bih1, bhh1, Wfc, bfc, out);
}

// round 2
// speedup vs baseline: 1.8017x; 1.8017x over previous
#include <cuda_runtime.h>
#include <cstdint>

#define BATCH 512
#define SEQ   512
#define EMB   128
#define HID   64
#define GATES 256   // 4*HID

// 268 MB scratch for xproj0 = emb[seq] @ Wih0^T + b0, layout [(b*SEQ+s)][GATES]
__device__ float g_xp0[(size_t)BATCH * SEQ * GATES];

// ---------------- packed f32x2 helpers ----------------
static __device__ __forceinline__ unsigned long long pk2(float lo, float hi) {
    unsigned long long v;
    asm("mov.b64 %0, {%1, %2};" : "=l"(v) : "f"(lo), "f"(hi));
    return v;
}
static __device__ __forceinline__ void upk2(unsigned long long v, float& lo, float& hi) {
    asm("mov.b64 {%0, %1}, %2;" : "=f"(lo), "=f"(hi) : "l"(v));
}
static __device__ __forceinline__ void fma2(unsigned long long& a,
                                            unsigned long long x,
                                            unsigned long long w) {
    asm("fma.rn.f32x2 %0, %1, %2, %0;" : "+l"(a) : "l"(x), "l"(w));
}
static __device__ __forceinline__ float tanh_f(float x) {
    float y;
    asm("tanh.approx.f32 %0, %1;" : "=f"(y) : "f"(x));
    return y;
}
static __device__ __forceinline__ float sig_f(float x) {
    return fmaf(0.5f, tanh_f(0.5f * x), 0.5f);
}

// ======================================================================
// Kernel 1: xproj0[row][g] = b0[g] + dot(emb[seq[row]], Wih0[g][:])
// 2048 blocks x 256 threads; each block: 4 tiles of 32 rows, Wih0 in smem.
// ======================================================================
#define K1_WS_STRIDE 132   // padded row stride for Wih0 in smem (bank-safe)

__global__ void __launch_bounds__(256)
k_xproj(const int* __restrict__ seq32,   // raw words of input_seq (int32 or int64)
        const float* __restrict__ emb,
        const float* __restrict__ Wih,
        const float* __restrict__ bih,
        const float* __restrict__ bhh,
        float* __restrict__ xp)
{
    extern __shared__ float sm[];
    float* ws   = sm;                         // 256 * 132
    float* xs   = ws + 256 * K1_WS_STRIDE;    // 32 * 128
    int*   sidx = (int*)(xs + 32 * EMB);      // 32

    const int tid = threadIdx.x;

    // Detect int64 vs int32 input_seq: int64 little-endian with values <2^31
    // has all-zero odd 32-bit words.
    const bool is64 = ((__ldg(seq32 + 1) | __ldg(seq32 + 3) | __ldg(seq32 + 5) |
                        __ldg(seq32 + 7) | __ldg(seq32 + 9) | __ldg(seq32 + 11) |
                        __ldg(seq32 + 13) | __ldg(seq32 + 15)) == 0);

    // Stage Wih0 into padded smem
    for (int j = tid; j < 256 * EMB; j += 256)
        ws[(j >> 7) * K1_WS_STRIDE + (j & 127)] = Wih[j];

    const float b0 = bih[tid] + bhh[tid];
    const int base = blockIdx.x * 128;

    for (int tile = 0; tile < 4; ++tile) {
        const int row0 = base + tile * 32;
        __syncthreads();                       // xs/ws reuse barrier
        if (tid < 32) {
            int row = row0 + tid;
            int idx = is64 ? __ldg(seq32 + 2 * row) : __ldg(seq32 + row);
            sidx[tid] = idx * EMB;
        }
        __syncthreads();
        // Gather 32 embedding rows
        for (int j = tid; j < 32 * 32; j += 256) {
            int r = j >> 5, k4 = (j & 31) << 2;
            *(float4*)&xs[r * EMB + k4] = *(const float4*)&emb[sidx[r] + k4];
        }
        __syncthreads();

        unsigned long long acc[32];
#pragma unroll
        for (int r = 0; r < 32; ++r) acc[r] = pk2(b0, 0.f);

#pragma unroll 2
        for (int kc = 0; kc < 32; ++kc) {
            const ulonglong2 w = *(const ulonglong2*)&ws[tid * K1_WS_STRIDE + kc * 4];
#pragma unroll
            for (int r = 0; r < 32; ++r) {
                const ulonglong2 x = *(const ulonglong2*)&xs[r * EMB + kc * 4];
                fma2(acc[r], x.x, w.x);
                fma2(acc[r], x.y, w.y);
            }
        }
#pragma unroll
        for (int r = 0; r < 32; ++r) {
            float lo, hi;
            upk2(acc[r], lo, hi);
            xp[(size_t)(row0 + r) * GATES + tid] = lo + hi;
        }
    }
}

// ======================================================================
// Kernel 2: fused 2-layer LSTM scan + final FC.
// 128 blocks x 256 threads; block b owns batch rows 4b..4b+3.
// ALL recurrent weights live in REGISTERS (thread tid owns gate tid's
// rows of Whh0, Wih1, Whh1: 3 x 64 floats = 96 f32x2 regs). Hidden state
// is double-buffered in smem (broadcast reads); gate exchange via two
// smem buffers. 3 barriers per step.
// ======================================================================
__global__ void __launch_bounds__(256, 1)
k_scan(const float* __restrict__ xp,
       const float* __restrict__ Whh0, const float* __restrict__ Wih1,
       const float* __restrict__ Whh1,
       const float* __restrict__ bih1, const float* __restrict__ bhh1,
       const float* __restrict__ Wfc,  const float* __restrict__ bfc,
       float* __restrict__ out)
{
    __shared__ float h0s[2][4 * HID];
    __shared__ float h1s[2][4 * HID];
    __shared__ float gA[4 * GATES];
    __shared__ float gB[4 * GATES];

    const int tid = threadIdx.x;

    // ---- load this thread's weight rows into registers (96 f32x2) ----
    unsigned long long w0[32], wi1[32], wh1[32];
#pragma unroll
    for (int j = 0; j < 16; ++j) {
        ulonglong2 v;
        v = *(const ulonglong2*)&Whh0[tid * HID + j * 4];
        w0[2 * j] = v.x;  w0[2 * j + 1] = v.y;
        v = *(const ulonglong2*)&Wih1[tid * HID + j * 4];
        wi1[2 * j] = v.x; wi1[2 * j + 1] = v.y;
        v = *(const ulonglong2*)&Whh1[tid * HID + j * 4];
        wh1[2 * j] = v.x; wh1[2 * j + 1] = v.y;
    }
    const float b1 = __ldg(&bih1[tid]) + __ldg(&bhh1[tid]);

    h0s[0][tid] = 0.f;
    h1s[0][tid] = 0.f;

    const int rr = tid >> 6, u = tid & 63;
    float c0 = 0.f, c1 = 0.f;
    const int row0 = blockIdx.x * 4;

    const float* p[4];
#pragma unroll
    for (int r = 0; r < 4; ++r)
        p[r] = xp + (size_t)(row0 + r) * SEQ * GATES + tid;

    __syncthreads();

    float xpc[4];
#pragma unroll
    for (int r = 0; r < 4; ++r) xpc[r] = __ldg(p[r]);

    for (int t = 0; t < SEQ; ++t) {
        const int cur = t & 1, nxt = cur ^ 1;

        // prefetch next step's xproj column
        float xpn[4] = {0.f, 0.f, 0.f, 0.f};
        if (t < SEQ - 1) {
#pragma unroll
            for (int r = 0; r < 4; ++r)
                xpn[r] = __ldg(p[r] + (size_t)(t + 1) * GATES);
        }

        // ---- Phase A: layer0 gates = xproj + h0 @ Whh0^T (weights in regs)
        unsigned long long a0[4];
#pragma unroll
        for (int r = 0; r < 4; ++r) a0[r] = pk2(xpc[r], 0.f);
#pragma unroll
        for (int kc = 0; kc < 16; ++kc) {
#pragma unroll
            for (int r = 0; r < 4; ++r) {
                const ulonglong2 h = *(const ulonglong2*)&h0s[cur][r * HID + kc * 4];
                fma2(a0[r], h.x, w0[2 * kc]);
                fma2(a0[r], h.y, w0[2 * kc + 1]);
            }
        }
#pragma unroll
        for (int r = 0; r < 4; ++r) {
            float lo, hi; upk2(a0[r], lo, hi);
            gA[r * GATES + tid] = lo + hi;
        }
        __syncthreads();   // (1) gA ready

        // ---- Phase B: layer0 elementwise, write h0[nxt]
        {
            const float* gr = gA + rr * GATES;
            float gi = sig_f(gr[u]);
            float gf = sig_f(gr[64 + u]);
            float gg = tanh_f(gr[128 + u]);
            float go = sig_f(gr[192 + u]);
            c0 = gf * c0 + gi * gg;
            h0s[nxt][rr * HID + u] = go * tanh_f(c0);
        }
        __syncthreads();   // (2) h0[nxt] ready

        // ---- Phase C: layer1 gates = b1 + h0new @ Wih1^T + h1 @ Whh1^T
        unsigned long long a1[4];
#pragma unroll
        for (int r = 0; r < 4; ++r) a1[r] = pk2(b1, 0.f);
#pragma unroll
        for (int kc = 0; kc < 16; ++kc) {
#pragma unroll
            for (int r = 0; r < 4; ++r) {
                const ulonglong2 h0v = *(const ulonglong2*)&h0s[nxt][r * HID + kc * 4];
                fma2(a1[r], h0v.x, wi1[2 * kc]);
                fma2(a1[r], h0v.y, wi1[2 * kc + 1]);
                const ulonglong2 h1v = *(const ulonglong2*)&h1s[cur][r * HID + kc * 4];
                fma2(a1[r], h1v.x, wh1[2 * kc]);
                fma2(a1[r], h1v.y, wh1[2 * kc + 1]);
            }
        }
#pragma unroll
        for (int r = 0; r < 4; ++r) {
            float lo, hi; upk2(a1[r], lo, hi);
            gB[r * GATES + tid] = lo + hi;
        }
        __syncthreads();   // (3) gB ready

        // ---- Phase D: layer1 elementwise, write h1[nxt]
        // (no trailing barrier: next-step barrier (1) orders h1[nxt] before
        //  its consumers; gA/gB double-buffering removes the other hazard)
        {
            const float* gr = gB + rr * GATES;
            float gi = sig_f(gr[u]);
            float gf = sig_f(gr[64 + u]);
            float gg = tanh_f(gr[128 + u]);
            float go = sig_f(gr[192 + u]);
            c1 = gf * c1 + gi * gg;
            h1s[nxt][rr * HID + u] = go * tanh_f(c1);
        }

#pragma unroll
        for (int r = 0; r < 4; ++r) xpc[r] = xpn[r];
    }
    __syncthreads();

    // ---- Final FC + sigmoid on last h1 (in buffer (SEQ-1)&1 ^ 1 = 0)
    if (tid < 8) {
        int r = tid >> 1, o = tid & 1;
        float a = __ldg(&bfc[o]);
        for (int k = 0; k < HID; ++k)
            a = fmaf(h1s[0][r * HID + k], __ldg(&Wfc[o * HID + k]), a);
        out[(row0 + r) * 2 + o] = sig_f(a);
    }
}

// ======================================================================
extern "C" void kernel_launch(void* const* d_in, const int* in_sizes, int n_in,
                              void* d_out, int out_size) {
    const int*   seq32 = (const int*)d_in[0];   // int32 or raw words of int64
    const float* emb   = (const float*)d_in[1];
    const float* Wih0  = (const float*)d_in[2];
    const float* Whh0  = (const float*)d_in[3];
    const float* bih0  = (const float*)d_in[4];
    const float* bhh0  = (const float*)d_in[5];
    const float* Wih1  = (const float*)d_in[6];
    const float* Whh1  = (const float*)d_in[7];
    const float* bih1  = (const float*)d_in[8];
    const float* bhh1  = (const float*)d_in[9];
    const float* Wfc   = (const float*)d_in[10];
    const float* bfc   = (const float*)d_in[11];
    float* out = (float*)d_out;

    float* xp = nullptr;
    cudaGetSymbolAddress((void**)&xp, g_xp0);

    const int smem1 = (256 * K1_WS_STRIDE + 32 * EMB) * 4 + 32 * 4;
    cudaFuncSetAttribute(k_xproj, cudaFuncAttributeMaxDynamicSharedMemorySize, smem1);

    k_xproj<<<(BATCH * SEQ) / 128, 256, smem1>>>(seq32, emb, Wih0, bih0, bhh0, xp);
    k_scan<<<BATCH / 4, 256>>>(xp, Whh0, Wih1, Whh1, bih1, bhh1, Wfc, bfc, out);
}

// round 4
// speedup vs baseline: 2.6874x; 1.4916x over previous
#include <cuda_runtime.h>
#include <cstdint>

#define BATCH 512
#define SEQ   512
#define EMB   128
#define HID   64
#define GATES 256   // 4*HID
#define VOCAB 50000

// 51.2 MB token->xproj table: table[v][g] = dot(emb[v], Wih0[g]) + bih0[g] + bhh0[g]
__device__ float g_tab[(size_t)VOCAB * GATES];

// ---------------- packed f32x2 helpers ----------------
static __device__ __forceinline__ unsigned long long pk2(float lo, float hi) {
    unsigned long long v;
    asm("mov.b64 %0, {%1, %2};" : "=l"(v) : "f"(lo), "f"(hi));
    return v;
}
static __device__ __forceinline__ void upk2(unsigned long long v, float& lo, float& hi) {
    asm("mov.b64 {%0, %1}, %2;" : "=f"(lo), "=f"(hi) : "l"(v));
}
static __device__ __forceinline__ void fma2(unsigned long long& a,
                                            unsigned long long x,
                                            unsigned long long w) {
    asm("fma.rn.f32x2 %0, %1, %2, %0;" : "+l"(a) : "l"(x), "l"(w));
}
static __device__ __forceinline__ float tanh_f(float x) {
    float y;
    asm("tanh.approx.f32 %0, %1;" : "=f"(y) : "f"(x));
    return y;
}
static __device__ __forceinline__ float sig_f(float x) {
    return fmaf(0.5f, tanh_f(0.5f * x), 0.5f);
}

// ======================================================================
// Kernel 1: token table build. table[v][g] = emb[v] . Wih0[g] + b0[g].
// Grid (391, 2): blockIdx.x = 128-row v-tile, blockIdx.y = gate half.
// 256 threads = 128 gates x 2 k-halves (adjacent lanes; shfl_xor reduce).
// Weights in registers (64 floats/thread); emb tiles staged in smem.
// ======================================================================
#define XT_STRIDE 136   // padded emb-tile row stride (floats); halves at 0 / 68

__global__ void __launch_bounds__(256, 2)
k_table(const float* __restrict__ emb,
        const float* __restrict__ Wih0,
        const float* __restrict__ bih0,
        const float* __restrict__ bhh0,
        float* __restrict__ tab)
{
    __shared__ float xs[16 * XT_STRIDE];

    const int tid  = threadIdx.x;
    const int gl   = tid >> 1;                  // 0..127
    const int half = tid & 1;
    const int g    = blockIdx.y * 128 + gl;     // global gate

    // this thread's 64 weight values: Wih0[g][half*64 .. half*64+64)
    unsigned long long w[32];
#pragma unroll
    for (int j = 0; j < 16; ++j) {
        ulonglong2 v = *(const ulonglong2*)&Wih0[g * EMB + half * 64 + j * 4];
        w[2 * j] = v.x;  w[2 * j + 1] = v.y;
    }
    const float b0 = (half == 0) ? (__ldg(&bih0[g]) + __ldg(&bhh0[g])) : 0.f;

    const int v0 = blockIdx.x * 128;

#pragma unroll 1
    for (int tile = 0; tile < 8; ++tile) {
        const int vbase = v0 + tile * 16;
        if (vbase >= VOCAB) break;
        const int rows = min(16, VOCAB - vbase);

        __syncthreads();
        // stage rows*128 floats, padded halves at 0 / 68
        for (int j = tid; j < rows * 32; j += 256) {
            const int r = j >> 5, k4 = j & 31;
            const int dst = r * XT_STRIDE + (k4 < 16 ? k4 * 4 : 68 + (k4 - 16) * 4);
            *(float4*)&xs[dst] = *(const float4*)&emb[(size_t)(vbase + r) * EMB + k4 * 4];
        }
        __syncthreads();

        unsigned long long acc[16];
#pragma unroll
        for (int r = 0; r < 16; ++r) acc[r] = pk2(b0, 0.f);

#pragma unroll
        for (int kc = 0; kc < 16; ++kc) {
#pragma unroll
            for (int r = 0; r < 16; ++r) {
                const ulonglong2 x = *(const ulonglong2*)&xs[r * XT_STRIDE + half * 68 + kc * 4];
                fma2(acc[r], x.x, w[2 * kc]);
                fma2(acc[r], x.y, w[2 * kc + 1]);
            }
        }
#pragma unroll
        for (int r = 0; r < 16; ++r) {
            float lo, hi; upk2(acc[r], lo, hi);
            float s = lo + hi;
            s += __shfl_xor_sync(0xFFFFFFFFu, s, 1);
            if (half == 0 && r < rows)
                tab[(size_t)(vbase + r) * GATES + g] = s;
        }
    }
}

// ======================================================================
// Kernel 2: fused 2-layer LSTM scan + final FC.
// 128 blocks x 512 threads; block b owns batch rows 4b..4b+3.
// Thread = (gate g = tid>>1, k-half = tid&1). Each thread holds 32-elem
// half-rows of Whh0/Wih1/Whh1 in regs (96 regs). Halves reduce via
// shfl_xor(1). h-state double-buffered, padded stride 136 (halves at
// 0/68) for conflict-free LDS.128. xproj gathered from token table with
// one-step prefetch. 3 barriers/step.
// ======================================================================
#define HS 136   // h row stride (floats): half0 at +0, half1 at +68

__global__ void __launch_bounds__(512, 1)
k_scan(const int* __restrict__ seq32,
       const float* __restrict__ tab,
       const float* __restrict__ Whh0, const float* __restrict__ Wih1,
       const float* __restrict__ Whh1,
       const float* __restrict__ bih1, const float* __restrict__ bhh1,
       const float* __restrict__ Wfc,  const float* __restrict__ bfc,
       float* __restrict__ out)
{
    __shared__ float h0s[2][4 * HS];
    __shared__ float h1s[2][4 * HS];
    __shared__ float gA[4 * GATES];
    __shared__ float gB[4 * GATES];
    __shared__ int4  tok4[SEQ];

    const int tid  = threadIdx.x;
    const int g    = tid >> 1;
    const int half = tid & 1;
    const int row0 = blockIdx.x * 4;

    // ---- weights: 3 half-rows of 32 floats each -> 48 f32x2 = 96 regs
    unsigned long long w0[16], wi1[16], wh1[16];
#pragma unroll
    for (int j = 0; j < 8; ++j) {
        ulonglong2 v;
        v = *(const ulonglong2*)&Whh0[g * HID + half * 32 + j * 4];
        w0[2 * j] = v.x;  w0[2 * j + 1] = v.y;
        v = *(const ulonglong2*)&Wih1[g * HID + half * 32 + j * 4];
        wi1[2 * j] = v.x; wi1[2 * j + 1] = v.y;
        v = *(const ulonglong2*)&Whh1[g * HID + half * 32 + j * 4];
        wh1[2 * j] = v.x; wh1[2 * j + 1] = v.y;
    }
    const float b1 = (half == 0) ? (__ldg(&bih1[g]) + __ldg(&bhh1[g])) : 0.f;

    // int64 vs int32 input_seq detection (values < 2^31 -> odd words zero)
    const bool is64 = ((__ldg(seq32 + 1) | __ldg(seq32 + 3) | __ldg(seq32 + 5) |
                        __ldg(seq32 + 7) | __ldg(seq32 + 9) | __ldg(seq32 + 11) |
                        __ldg(seq32 + 13) | __ldg(seq32 + 15)) == 0);

    // ---- stage this block's tokens: tok4[t] = tokens of rows row0..row0+3
    {
        const int t = tid;
        if (t < SEQ) {
            int4 v;
            if (is64) {
                v.x = __ldg(seq32 + 2 * ((row0 + 0) * SEQ + t));
                v.y = __ldg(seq32 + 2 * ((row0 + 1) * SEQ + t));
                v.z = __ldg(seq32 + 2 * ((row0 + 2) * SEQ + t));
                v.w = __ldg(seq32 + 2 * ((row0 + 3) * SEQ + t));
            } else {
                v.x = __ldg(seq32 + (row0 + 0) * SEQ + t);
                v.y = __ldg(seq32 + (row0 + 1) * SEQ + t);
                v.z = __ldg(seq32 + (row0 + 2) * SEQ + t);
                v.w = __ldg(seq32 + (row0 + 3) * SEQ + t);
            }
            tok4[t] = v;
        }
    }
    for (int j = tid; j < 4 * HS; j += 512) {
        h0s[0][j] = 0.f;
        h1s[0][j] = 0.f;
    }

    const int rr = (tid & 255) >> 6, u = tid & 63;   // elementwise mapping (tid<256)
    float c0 = 0.f, c1 = 0.f;

    __syncthreads();

    // initial xproj gather (half0 only carries real values)
    float xpc[4] = {0.f, 0.f, 0.f, 0.f};
    if (half == 0) {
        const int4 tk = tok4[0];
        xpc[0] = __ldg(&tab[(size_t)tk.x * GATES + g]);
        xpc[1] = __ldg(&tab[(size_t)tk.y * GATES + g]);
        xpc[2] = __ldg(&tab[(size_t)tk.z * GATES + g]);
        xpc[3] = __ldg(&tab[(size_t)tk.w * GATES + g]);
    }

    for (int t = 0; t < SEQ; ++t) {
        const int cur = t & 1, nxt = cur ^ 1;

        // prefetch next step's xproj (covered by ~1 full step of latency)
        float xpn[4] = {0.f, 0.f, 0.f, 0.f};
        if (half == 0 && t < SEQ - 1) {
            const int4 tk = tok4[t + 1];
            xpn[0] = __ldg(&tab[(size_t)tk.x * GATES + g]);
            xpn[1] = __ldg(&tab[(size_t)tk.y * GATES + g]);
            xpn[2] = __ldg(&tab[(size_t)tk.z * GATES + g]);
            xpn[3] = __ldg(&tab[(size_t)tk.w * GATES + g]);
        }

        // ---- Phase A: layer0 partial gates over this k-half
        unsigned long long a0[4];
#pragma unroll
        for (int r = 0; r < 4; ++r) a0[r] = pk2(xpc[r], 0.f);
#pragma unroll
        for (int kc = 0; kc < 8; ++kc) {
#pragma unroll
            for (int r = 0; r < 4; ++r) {
                const ulonglong2 h = *(const ulonglong2*)&h0s[cur][r * HS + half * 68 + kc * 4];
                fma2(a0[r], h.x, w0[2 * kc]);
                fma2(a0[r], h.y, w0[2 * kc + 1]);
            }
        }
#pragma unroll
        for (int r = 0; r < 4; ++r) {
            float lo, hi; upk2(a0[r], lo, hi);
            float s = lo + hi;
            s += __shfl_xor_sync(0xFFFFFFFFu, s, 1);
            if (half == 0) gA[r * GATES + g] = s;
        }
        __syncthreads();   // (1) gA ready

        // ---- Phase B: layer0 elementwise (threads 0..255)
        if (tid < 256) {
            const float* gr = gA + rr * GATES;
            float gi = sig_f(gr[u]);
            float gf = sig_f(gr[64 + u]);
            float gg = tanh_f(gr[128 + u]);
            float go = sig_f(gr[192 + u]);
            c0 = gf * c0 + gi * gg;
            h0s[nxt][rr * HS + (u >> 5) * 68 + (u & 31)] = go * tanh_f(c0);
        }
        __syncthreads();   // (2) h0[nxt] ready

        // ---- Phase C: layer1 partial gates over this k-half
        unsigned long long a1[4];
#pragma unroll
        for (int r = 0; r < 4; ++r) a1[r] = pk2(b1, 0.f);
#pragma unroll
        for (int kc = 0; kc < 8; ++kc) {
#pragma unroll
            for (int r = 0; r < 4; ++r) {
                const ulonglong2 h0v = *(const ulonglong2*)&h0s[nxt][r * HS + half * 68 + kc * 4];
                fma2(a1[r], h0v.x, wi1[2 * kc]);
                fma2(a1[r], h0v.y, wi1[2 * kc + 1]);
                const ulonglong2 h1v = *(const ulonglong2*)&h1s[cur][r * HS + half * 68 + kc * 4];
                fma2(a1[r], h1v.x, wh1[2 * kc]);
                fma2(a1[r], h1v.y, wh1[2 * kc + 1]);
            }
        }
#pragma unroll
        for (int r = 0; r < 4; ++r) {
            float lo, hi; upk2(a1[r], lo, hi);
            float s = lo + hi;
            s += __shfl_xor_sync(0xFFFFFFFFu, s, 1);
            if (half == 0) gB[r * GATES + g] = s;
        }
        __syncthreads();   // (3) gB ready

        // ---- Phase D: layer1 elementwise (no trailing barrier; barrier (1)
        //      of the next step orders h1[nxt] / gB reuse)
        if (tid < 256) {
            const float* gr = gB + rr * GATES;
            float gi = sig_f(gr[u]);
            float gf = sig_f(gr[64 + u]);
            float gg = tanh_f(gr[128 + u]);
            float go = sig_f(gr[192 + u]);
            c1 = gf * c1 + gi * gg;
            h1s[nxt][rr * HS + (u >> 5) * 68 + (u & 31)] = go * tanh_f(c1);
        }

#pragma unroll
        for (int r = 0; r < 4; ++r) xpc[r] = xpn[r];
    }
    __syncthreads();

    // ---- Final FC + sigmoid on last h1 (buffer 0 after even SEQ)
    if (tid < 8) {
        int r = tid >> 1, o = tid & 1;
        float a = __ldg(&bfc[o]);
        for (int k = 0; k < HID; ++k)
            a = fmaf(h1s[0][r * HS + (k >> 5) * 68 + (k & 31)],
                     __ldg(&Wfc[o * HID + k]), a);
        out[(row0 + r) * 2 + o] = sig_f(a);
    }
}

// ======================================================================
extern "C" void kernel_launch(void* const* d_in, const int* in_sizes, int n_in,
                              void* d_out, int out_size) {
    const int*   seq32 = (const int*)d_in[0];   // int32 or raw words of int64
    const float* emb   = (const float*)d_in[1];
    const float* Wih0  = (const float*)d_in[2];
    const float* Whh0  = (const float*)d_in[3];
    const float* bih0  = (const float*)d_in[4];
    const float* bhh0  = (const float*)d_in[5];
    const float* Wih1  = (const float*)d_in[6];
    const float* Whh1  = (const float*)d_in[7];
    const float* bih1  = (const float*)d_in[8];
    const float* bhh1  = (const float*)d_in[9];
    const float* Wfc   = (const float*)d_in[10];
    const float* bfc   = (const float*)d_in[11];
    float* out = (float*)d_out;

    float* tab = nullptr;
    cudaGetSymbolAddress((void**)&tab, g_tab);

    dim3 gtab((VOCAB + 127) / 128, 2);
    k_table<<<gtab, 256>>>(emb, Wih0, bih0, bhh0, tab);
    k_scan<<<BATCH / 4, 512>>>(seq32, tab, Whh0, Wih1, Whh1,
                               bih1, bhh1, Wfc, bfc, out);
}